// round 9
// baseline (speedup 1.0000x reference)
#include <cuda_runtime.h>

// ValueLayerSlow: Pauli expectations, 16 strings, 10 qubits (dim=1024),
// real states (4096 of them).
//   Z on d-bit b (op o -> bit 9-o): sum_d (-1)^{bit_b(d)} x_d^2
//   X masks 512/256/128 (ops 10,11,12): 2 * sum_{pairs} x_d x_{d^m}
//   Y ops (13,14,15): exactly 0.
//
// R8 resubmit (prior round was an infra failure, not a kernel failure):
// TWO warps per state, split on j (low 2 bits of d): warp q holds
// j in {2q, 2q+1} -> element pair d = i*128 + lane*4 + 2q + {0,1}.
// All X masks flip only i bits and all other Z structures are j-independent,
// so each warp runs the FULL R7 pipeline on its half (float2 loads) and the
// only cross-warp step is one 16-float add at the very end (smem + 1 sync).
// z1 (j bit1 Z) = +S for warp0, -S for warp1. Occupancy doubles (8192 warps).

__global__ void __launch_bounds__(128)
pauli_expect_kernel(const float* __restrict__ x, float* __restrict__ out,
                    int n_states) {
    __shared__ float part[2][16];          // warp-1 partial val per state pair

    const int tid   = threadIdx.x;
    const int lane  = tid & 31;
    const int wid   = tid >> 5;            // 0..3
    const int pair  = wid >> 1;            // state slot within block (0,1)
    const int q     = wid & 1;             // j-half: 0 -> j{0,1}, 1 -> j{2,3}
    const int state = blockIdx.x * 2 + pair;
    if (state >= n_states) return;

    // float2 index: byte addr = state*4096 + i*512 + 16*lane + 8*q
    const float2* xp = reinterpret_cast<const float2*>(x)
                     + (size_t)state * 512 + lane * 2 + q;

    float2 v[8];
    float s[8];
    float z0 = 0.f;                        // op9 partial: sign from j bit0

#define SQ(i) { float a0 = v[i].x * v[i].x, a1 = v[i].y * v[i].y;          \
                s[i] = a0 + a1; z0 += a0 - a1; }

    // ---- batch 1: loads + squares (MLP_p1 = 4) ----
#pragma unroll
    for (int i = 0; i < 4; i++) v[i] = __ldcs(&xp[i * 64]);
    SQ(0) SQ(1) SQ(2) SQ(3)

    asm volatile("" ::: "memory");

    // ---- batch 2 ----
#pragma unroll
    for (int i = 4; i < 8; i++) v[i] = __ldcs(&xp[i * 64]);
    SQ(4) SQ(5) SQ(6) SQ(7)
#undef SQ

    float e01 = s[0] + s[1], e23 = s[2] + s[3];
    float e45 = s[4] + s[5], e67 = s[6] + s[7];
    float S  = (e01 + e23) + (e45 + e67);          // warp's sum of squares
    float z9 = (e01 + e23) - (e45 + e67);          // op0 partial (i bit2)
    float z8 = (e01 + e45) - (e23 + e67);          // op1 partial (i bit1)
    float z7 = ((s[0] + s[2]) + (s[4] + s[6]))
             - ((s[1] + s[3]) + (s[5] + s[7]));    // op2 partial (i bit0)
    float z1 = q ? -S : S;                         // op8 partial (j bit1)

    // ---- X dots on float2 halves (pair structure over i unchanged) ----
#define DOT2(a, b) ((a).x*(b).x + (a).y*(b).y)
    float x9 = DOT2(v[0], v[4]) + DOT2(v[1], v[5])
             + DOT2(v[2], v[6]) + DOT2(v[3], v[7]);   // mask 512
    float x8 = DOT2(v[0], v[2]) + DOT2(v[1], v[3])
             + DOT2(v[4], v[6]) + DOT2(v[5], v[7]);   // mask 256
    float x7 = DOT2(v[0], v[1]) + DOT2(v[2], v[3])
             + DOT2(v[4], v[5]) + DOT2(v[6], v[7]);   // mask 128
#undef DOT2

    // ---- 8 interleaved butterfly all-reduces ----
    const unsigned FULL = 0xFFFFFFFFu;
#pragma unroll
    for (int o = 16; o > 0; o >>= 1) {
        z9 += __shfl_xor_sync(FULL, z9, o);
        z8 += __shfl_xor_sync(FULL, z8, o);
        z7 += __shfl_xor_sync(FULL, z7, o);
        z1 += __shfl_xor_sync(FULL, z1, o);
        z0 += __shfl_xor_sync(FULL, z0, o);
        x9 += __shfl_xor_sync(FULL, x9, o);
        x8 += __shfl_xor_sync(FULL, x8, o);
        x7 += __shfl_xor_sync(FULL, x7, o);
    }

    // ---- Walsh-Hadamard over S: lane 2^k holds Z on d-bit (k+2) = op (7-k)
    float w = S;
#pragma unroll
    for (int k = 0; k < 5; k++) {
        float p = __shfl_xor_sync(FULL, w, 1 << k);
        w = (lane & (1 << k)) ? (p - w) : (p + w);
    }
    // route WH results to output lanes 3..7: op l <- WH lane 2^(7-l)
    int src = (lane >= 3 && lane < 8) ? (1 << (7 - lane)) : 0;
    float wmv = __shfl_sync(FULL, w, src);

    // ---- per-warp 16-lane partial result vector ----
    float val = (lane < 3)  ? (lane == 0 ? z9 : lane == 1 ? z8 : z7)
              : (lane < 8)  ? wmv
              : (lane < 10) ? (lane == 8 ? z1 : z0)
              : (lane < 13) ? 2.0f * (lane == 10 ? x9 : lane == 11 ? x8 : x7)
              : 0.0f;                             // ops 13,14,15 (Y) = 0

    // ---- combine the two j-halves: warp1 publishes, warp0 adds + stores ----
    if (q == 1 && lane < 16) part[pair][lane] = val;
    __syncthreads();
    if (q == 0 && lane < 16)
        out[(size_t)state * 16 + lane] = val + part[pair][lane];
}

extern "C" void kernel_launch(void* const* d_in, const int* in_sizes, int n_in,
                              void* d_out, int out_size) {
    const float* x = (const float*)d_in[0];
    float* out = (float*)d_out;
    const int n_states = in_sizes[0] / 1024;     // 4096 for (8,512,1024)
    const int blocks = (n_states + 1) / 2;       // 2 states (4 warps) / block
    pauli_expect_kernel<<<blocks, 128>>>(x, out, n_states);
}

// round 10
// speedup vs baseline: 1.2188x; 1.2188x over previous
#include <cuda_runtime.h>

// ValueLayerSlow: Pauli expectation values <psi|O|psi> for 16 Pauli strings on
// 10 qubits (dim=1024), states are REAL vectors (8*512 = 4096 states).
//
// Algebraic reduction (states real):
//   Z on bit b (ops 0..9, op o -> bit 9-o):  sum_d (-1)^{bit_b(d)} x_d^2
//   X on bit b (ops 10,11,12 -> masks 512/256/128): 2*sum_{pairs} x_d x_{d^m}
//   Y ops (13,14,15): exactly 0.
//
// One warp per state. Lane t holds d = i*128 + t*4 + j (8 x float4).
// R10 = R7 (measured-fastest structure: split 4+4 loads, butterfly
// all-reduce, one coalesced STG across lanes 0..15) with ONE change:
// plain loads instead of __ldcs. The timed loop replays the same graph;
// the 16.8 MB input fits in L2 (~126 MB), so evict-normal policy keeps x
// L2-resident across replays (234-262 cyc) where __ldcs (evict-first)
// forced every replay back to DRAM (577 cyc).

__global__ void __launch_bounds__(128)
pauli_expect_kernel(const float* __restrict__ x, float* __restrict__ out,
                    int n_states) {
    const int warp = (blockIdx.x * blockDim.x + threadIdx.x) >> 5;
    const int lane = threadIdx.x & 31;
    if (warp >= n_states) return;

    const float4* xp = reinterpret_cast<const float4*>(x) + (size_t)warp * 256;

    float4 v[8];
    float s[8];
    float z1 = 0.f;  // op8: Z on bit1 (sign from j>>1)
    float z0 = 0.f;  // op9: Z on bit0 (sign from j&1)

#define SQ(i) { float a0 = v[i].x * v[i].x, a1 = v[i].y * v[i].y;          \
                float a2 = v[i].z * v[i].z, a3 = v[i].w * v[i].w;          \
                float p01 = a0 + a1, p23 = a2 + a3;                        \
                s[i] = p01 + p23;                                          \
                z1 += p01 - p23; z0 += (a0 - a1) + (a2 - a3); }

    // ---- batch 1: loads + squares (MLP_p1 = 4) ----
#pragma unroll
    for (int i = 0; i < 4; i++) v[i] = xp[i * 32 + lane];
    SQ(0) SQ(1) SQ(2) SQ(3)

    // compiler fence: keep batch-2 loads behind batch-1 compute in PTX order
    asm volatile("" ::: "memory");

    // ---- batch 2: loads + squares ----
#pragma unroll
    for (int i = 4; i < 8; i++) v[i] = xp[i * 32 + lane];
    SQ(4) SQ(5) SQ(6) SQ(7)
#undef SQ

    float e01 = s[0] + s[1], e23 = s[2] + s[3];
    float e45 = s[4] + s[5], e67 = s[6] + s[7];
    float S  = (e01 + e23) + (e45 + e67);          // total sum of squares
    float z9 = (e01 + e23) - (e45 + e67);          // op0: Z bit9 (i bit2)
    float z8 = (e01 + e45) - (e23 + e67);          // op1: Z bit8 (i bit1)
    float z7 = ((s[0] + s[2]) + (s[4] + s[6]))
             - ((s[1] + s[3]) + (s[5] + s[7]));    // op2: Z bit7 (i bit0)

    // ---- X ops: register-resident pair dots (each unordered pair once)
#define DOT4(a, b) ((a).x*(b).x + (a).y*(b).y + (a).z*(b).z + (a).w*(b).w)
    float x9 = DOT4(v[0], v[4]) + DOT4(v[1], v[5])
             + DOT4(v[2], v[6]) + DOT4(v[3], v[7]);   // mask 512 (op10)
    float x8 = DOT4(v[0], v[2]) + DOT4(v[1], v[3])
             + DOT4(v[4], v[6]) + DOT4(v[5], v[7]);   // mask 256 (op11)
    float x7 = DOT4(v[0], v[1]) + DOT4(v[2], v[3])
             + DOT4(v[4], v[5]) + DOT4(v[6], v[7]);   // mask 128 (op12)
#undef DOT4

    // ---- 8 interleaved butterfly all-reduces (totals land in EVERY lane) ----
    const unsigned FULL = 0xFFFFFFFFu;
#pragma unroll
    for (int o = 16; o > 0; o >>= 1) {
        z9 += __shfl_xor_sync(FULL, z9, o);
        z8 += __shfl_xor_sync(FULL, z8, o);
        z7 += __shfl_xor_sync(FULL, z7, o);
        z1 += __shfl_xor_sync(FULL, z1, o);
        z0 += __shfl_xor_sync(FULL, z0, o);
        x9 += __shfl_xor_sync(FULL, x9, o);
        x8 += __shfl_xor_sync(FULL, x8, o);
        x7 += __shfl_xor_sync(FULL, x7, o);
    }

    // ---- Walsh-Hadamard over S: lane 2^k holds Z on d-bit (k+2) = op (7-k)
    float w = S;
#pragma unroll
    for (int k = 0; k < 5; k++) {
        float p = __shfl_xor_sync(FULL, w, 1 << k);
        w = (lane & (1 << k)) ? (p - w) : (p + w);
    }
    // route WH results to output lanes 3..7: op l <- WH lane 2^(7-l)
    int src = (lane >= 3 && lane < 8) ? (1 << (7 - lane)) : 0;
    float wmv = __shfl_sync(FULL, w, src);

    // ---- one coalesced STG.32: out[warp*16 + lane], lanes 0..15 ----
    float val = (lane < 3)  ? (lane == 0 ? z9 : lane == 1 ? z8 : z7)
              : (lane < 8)  ? wmv
              : (lane < 10) ? (lane == 8 ? z1 : z0)
              : (lane < 13) ? 2.0f * (lane == 10 ? x9 : lane == 11 ? x8 : x7)
              : 0.0f;                             // ops 13,14,15 (Y) = 0
    if (lane < 16) out[(size_t)warp * 16 + lane] = val;
}

extern "C" void kernel_launch(void* const* d_in, const int* in_sizes, int n_in,
                              void* d_out, int out_size) {
    const float* x = (const float*)d_in[0];
    float* out = (float*)d_out;
    const int n_states = in_sizes[0] / 1024;     // 4096 for (8,512,1024)
    const int blocks = (n_states + 3) / 4;       // 4 warps (128 thr) per block
    pauli_expect_kernel<<<blocks, 128>>>(x, out, n_states);
}

// round 12
// speedup vs baseline: 1.2409x; 1.0182x over previous
#include <cuda_runtime.h>

// ValueLayerSlow: Pauli expectation values <psi|O|psi> for 16 Pauli strings on
// 10 qubits (dim=1024), states are REAL vectors (8*512 = 4096 states).
//
// Algebraic reduction (states real):
//   Z on bit b (ops 0..9, op o -> bit 9-o):  sum_d (-1)^{bit_b(d)} x_d^2
//   X on bit b (ops 10,11,12 -> masks 512/256/128): 2*sum_{pairs} x_d x_{d^m}
//   Y ops (13,14,15): exactly 0.
//
// One warp per state. Lane t holds d = i*128 + t*4 + j (8 x float4).
// R11 resubmit (prior round was an infra failure): R7 structure with the
// 8-scalar reduction as a split-merge tree (9 shuffles vs 40). Per-warp SHFL
// count 46 -> 16. Scalar k lands fully reduced in lanes 4*bitrev3(k)+{0..3};
// one indexed shuffle routes to output lanes.

// merge2: butterfly stage reducing a and b over `bit` while splitting their
// identity across that lane bit. Lanes with (lane&bit)==0 end with
// a_L + a_{L^bit}; lanes with the bit set end with b_L + b_{L^bit}.
__device__ __forceinline__ float merge2(float a, float b, int bit, int lane) {
    bool hi = (lane & bit) != 0;
    float keep = hi ? b : a;
    float send = hi ? a : b;
    float recv = __shfl_xor_sync(0xFFFFFFFFu, send, bit);
    return keep + recv;
}

__global__ void __launch_bounds__(128)
pauli_expect_kernel(const float* __restrict__ x, float* __restrict__ out,
                    int n_states) {
    const int warp = (blockIdx.x * blockDim.x + threadIdx.x) >> 5;
    const int lane = threadIdx.x & 31;
    if (warp >= n_states) return;

    const float4* xp = reinterpret_cast<const float4*>(x) + (size_t)warp * 256;

    float4 v[8];
    float s[8];
    float z1 = 0.f;  // op8: Z on bit1 (sign from j>>1)
    float z0 = 0.f;  // op9: Z on bit0 (sign from j&1)

#define SQ(i) { float a0 = v[i].x * v[i].x, a1 = v[i].y * v[i].y;          \
                float a2 = v[i].z * v[i].z, a3 = v[i].w * v[i].w;          \
                float p01 = a0 + a1, p23 = a2 + a3;                        \
                s[i] = p01 + p23;                                          \
                z1 += p01 - p23; z0 += (a0 - a1) + (a2 - a3); }

    // ---- batch 1: loads + squares (MLP_p1 = 4) ----
#pragma unroll
    for (int i = 0; i < 4; i++) v[i] = xp[i * 32 + lane];
    SQ(0) SQ(1) SQ(2) SQ(3)

    asm volatile("" ::: "memory");

    // ---- batch 2: loads + squares ----
#pragma unroll
    for (int i = 4; i < 8; i++) v[i] = xp[i * 32 + lane];
    SQ(4) SQ(5) SQ(6) SQ(7)
#undef SQ

    float e01 = s[0] + s[1], e23 = s[2] + s[3];
    float e45 = s[4] + s[5], e67 = s[6] + s[7];
    float S  = (e01 + e23) + (e45 + e67);          // total sum of squares
    float z9 = (e01 + e23) - (e45 + e67);          // op0: Z bit9 (i bit2)
    float z8 = (e01 + e45) - (e23 + e67);          // op1: Z bit8 (i bit1)
    float z7 = ((s[0] + s[2]) + (s[4] + s[6]))
             - ((s[1] + s[3]) + (s[5] + s[7]));    // op2: Z bit7 (i bit0)

    // ---- X ops: register-resident pair dots (each unordered pair once)
#define DOT4(a, b) ((a).x*(b).x + (a).y*(b).y + (a).z*(b).z + (a).w*(b).w)
    float x9 = DOT4(v[0], v[4]) + DOT4(v[1], v[5])
             + DOT4(v[2], v[6]) + DOT4(v[3], v[7]);   // mask 512 (op10)
    float x8 = DOT4(v[0], v[2]) + DOT4(v[1], v[3])
             + DOT4(v[4], v[6]) + DOT4(v[5], v[7]);   // mask 256 (op11)
    float x7 = DOT4(v[0], v[1]) + DOT4(v[2], v[3])
             + DOT4(v[4], v[5]) + DOT4(v[6], v[7]);   // mask 128 (op12)
#undef DOT4

    // ---- split-merge reduction: 9 shuffles for all 8 scalars ----
    // identity bits after merging: bit16 (inner), bit8, bit4.
    const unsigned FULL = 0xFFFFFFFFu;
    float m0 = merge2(z9, z8, 16, lane);   // bit16: 0->z9 1->z8
    float m1 = merge2(z7, z1, 16, lane);   //        0->z7 1->z1
    float m2 = merge2(z0, x9, 16, lane);   //        0->z0 1->x9
    float m3 = merge2(x8, x7, 16, lane);   //        0->x8 1->x7
    float n0 = merge2(m0, m1, 8, lane);    // bit8:  0->m0 1->m1
    float n1 = merge2(m2, m3, 8, lane);
    float q  = merge2(n0, n1, 4, lane);    // bit4:  0->n0 1->n1
    q += __shfl_xor_sync(FULL, q, 2);
    q += __shfl_xor_sync(FULL, q, 1);
    // scalar k (order z9,z8,z7,z1,z0,x9,x8,x7 = k 0..7) sits in lanes
    // 4*bitrev3(k) + {0..3}:  z9@0 z8@16 z7@8 z1@24 z0@4 x9@20 x8@12 x7@28

    // ---- Walsh-Hadamard over S: lane 2^k holds Z on d-bit (k+2) = op (7-k)
    float w = S;
#pragma unroll
    for (int k = 0; k < 5; k++) {
        float p = __shfl_xor_sync(FULL, w, 1 << k);
        w = (lane & (1 << k)) ? (p - w) : (p + w);
    }
    // route: output lanes 3..7 take w from lane 2^(7-lane)
    int srcw = (lane >= 3 && lane < 8) ? (1 << (7 - lane)) : 0;
    float wmv = __shfl_sync(FULL, w, srcw);

    // route q: output order [z9,z8,z7,z1,z0,x9,x8,x7] at lanes {0,1,2,8..12};
    // result index k = lane (<3) or lane-5; source lane = 4*bitrev3(k).
    int k   = (lane < 3) ? lane : (lane - 5);
    int srq = (((k & 1) << 2) | (k & 2) | ((k & 4) >> 2)) << 2;
    float qv = __shfl_sync(FULL, q, srq & 31);

    // ---- one coalesced STG.32: out[warp*16 + lane], lanes 0..15 ----
    float val = (lane < 3)  ? qv
              : (lane < 8)  ? wmv
              : (lane < 10) ? qv
              : (lane < 13) ? 2.0f * qv
              : 0.0f;                             // ops 13,14,15 (Y) = 0
    if (lane < 16) out[(size_t)warp * 16 + lane] = val;
}

extern "C" void kernel_launch(void* const* d_in, const int* in_sizes, int n_in,
                              void* d_out, int out_size) {
    const float* x = (const float*)d_in[0];
    float* out = (float*)d_out;
    const int n_states = in_sizes[0] / 1024;     // 4096 for (8,512,1024)
    const int blocks = (n_states + 3) / 4;       // 4 warps (128 thr) per block
    pauli_expect_kernel<<<blocks, 128>>>(x, out, n_states);
}